// round 11
// baseline (speedup 1.0000x reference)
#include <cuda_runtime.h>
#include <cuda_bf16.h>
#include <cuda_fp16.h>
#include <cstdint>

#define NI 40000
#define NU 30000
#define NF 30000
#define NN 100000
#define EE 1200000
#define ET (EE + NN)
#define NEG 0.2f

// ---- output layout (tuple order, flattened) ----
static const size_t OFF_ITEM  = 0;
static const size_t OFF_USER  = OFF_ITEM + (size_t)NI * 64;
static const size_t OFF_FET   = OFF_USER + (size_t)NU * 64;
static const size_t OFF_FINAL = OFF_FET  + (size_t)NF * 64;
static const size_t OFF_A1    = OFF_FINAL + (size_t)NN * 64;
static const size_t OFF_A2    = OFF_A1 + (size_t)ET * 2;
static const size_t OFF_A3    = OFF_A2 + (size_t)ET * 2;

// ---- scratch (device globals; no allocation allowed) ----
__device__ __half g_xwh[(size_t)NN * 128];   // fp16 xw: only consumer is the gather
__device__ float g_x1[(size_t)NN * 128];
__device__ float g_x2[(size_t)NN * 128];
__device__ float g_x3[(size_t)NN * 64];
__device__ float g_as[(size_t)NN * 2];
__device__ float g_ad[(size_t)NN * 2];
__device__ float g_esc[(size_t)ET * 2];   // slow-path edge scores
__device__ int   g_cnt[NN];
__device__ int   g_off[NN + 1];
__device__ int   g_cur[NN];
__device__ int   g_eid[ET];
__device__ int   g_srcid[ET];
__device__ int   g_bsum[128];

__device__ __forceinline__ int edge_src(const int* ei, int e) {
    return (e < EE) ? ei[e] : (e - EE);
}
__device__ __forceinline__ int edge_dst(const int* ei, int e) {
    return (e < EE) ? ei[EE + e] : (e - EE);
}
__device__ __forceinline__ float lrelu(float x) { return x > 0.f ? x : NEG * x; }

// ---- bf16 split helpers (GEMM inputs) ----
__device__ __forceinline__ void bf_hilo(float x, float& h, float& l) {
    __nv_bfloat16 hb = __float2bfloat16_rn(x);
    h = __bfloat162float(hb);
    l = x - h;
}
__device__ __forceinline__ uint32_t bfpack(float lo_elem, float hi_elem) {
    __nv_bfloat162 t = __floats2bfloat162_rn(lo_elem, hi_elem);
    return *(uint32_t*)&t;
}
__device__ __forceinline__ void mma16(float* d, const uint32_t* a, const uint32_t* b) {
    asm volatile(
        "mma.sync.aligned.m16n8k16.row.col.f32.bf16.bf16.f32 "
        "{%0,%1,%2,%3}, {%4,%5,%6,%7}, {%8,%9}, {%0,%1,%2,%3};"
        : "+f"(d[0]), "+f"(d[1]), "+f"(d[2]), "+f"(d[3])
        : "r"(a[0]), "r"(a[1]), "r"(a[2]), "r"(a[3]), "r"(b[0]), "r"(b[1]));
}

// ================= CSR build =================
__global__ void k_zero_cnt() {
    int i = blockIdx.x * blockDim.x + threadIdx.x;
    if (i < NN) g_cnt[i] = 0;
}

__global__ void k_count(const int* __restrict__ ei) {
    for (int e = blockIdx.x * blockDim.x + threadIdx.x; e < ET;
         e += gridDim.x * blockDim.x)
        atomicAdd(&g_cnt[edge_dst(ei, e)], 1);
}

__global__ void k_scan1() {
    __shared__ int sh[1024];
    int i = blockIdx.x * 1024 + threadIdx.x;
    int v = (i < NN) ? g_cnt[i] : 0;
    sh[threadIdx.x] = v;
    __syncthreads();
    for (int o = 1; o < 1024; o <<= 1) {
        int t = (threadIdx.x >= (unsigned)o) ? sh[threadIdx.x - o] : 0;
        __syncthreads();
        sh[threadIdx.x] += t;
        __syncthreads();
    }
    if (i < NN) g_off[i + 1] = sh[threadIdx.x];
    if (threadIdx.x == 1023) g_bsum[blockIdx.x] = sh[1023];
}

__global__ void k_scan2(int nb) {
    __shared__ int sh[128];
    int v = ((int)threadIdx.x < nb) ? g_bsum[threadIdx.x] : 0;
    sh[threadIdx.x] = v;
    __syncthreads();
    for (int o = 1; o < 128; o <<= 1) {
        int t = (threadIdx.x >= (unsigned)o) ? sh[threadIdx.x - o] : 0;
        __syncthreads();
        sh[threadIdx.x] += t;
        __syncthreads();
    }
    if ((int)threadIdx.x < nb) g_bsum[threadIdx.x] = sh[threadIdx.x] - v;
}

__global__ void k_scan3() {
    int i = blockIdx.x * 1024 + threadIdx.x;
    if (i < NN) {
        int v = g_off[i + 1] + g_bsum[blockIdx.x];
        g_off[i + 1] = v;
        if (i + 1 < NN) g_cur[i + 1] = v;
    }
    if (i == 0) { g_off[0] = 0; g_cur[0] = 0; }
}

__global__ void k_scatter(const int* __restrict__ ei) {
    for (int e = blockIdx.x * blockDim.x + threadIdx.x; e < ET;
         e += gridDim.x * blockDim.x) {
        int s = edge_src(ei, e);
        int d = edge_dst(ei, e);
        int pos = atomicAdd(&g_cur[d], 1);
        g_eid[pos] = e;
        g_srcid[pos] = s;
    }
}

// ========== 3xBF16 mma.sync GEMM (m16n8k16): 256 thr, warp tile 32x64 ==========
// NCP = NC+8: B-fragment reads bank-conflict-free (stride ≡ 8 mod 32).
// Epilogue: write g_xwh (fp16) + fused att dots.
template <int KD, int NC, int AMODE, int H>
__global__ void __launch_bounds__(256, 2)
k_gemm_mma(const float* __restrict__ Ei, const float* __restrict__ Eu,
           const float* __restrict__ Ef, const float* __restrict__ W,
           const float* __restrict__ att_s, const float* __restrict__ att_d) {
    constexpr int BM = 128, KC = 32;
    constexpr int KAP = KC / 2 + 4;      // 20: A stride, conflict-free
    constexpr int NCP = NC + 8;          // B stride ≡ 8 mod 32: conflict-free
    constexpr int WN = NC / 2;
    constexpr int AN = WN / 8;
    constexpr int A_ELEM = BM * KAP;
    constexpr int B_ELEM = (KC / 2) * NCP;

    extern __shared__ uint32_t smu[];
    uint32_t* As_h = smu;
    uint32_t* As_l = As_h + A_ELEM;
    uint32_t* Bs_h = As_l + A_ELEM;
    uint32_t* Bs_l = Bs_h + B_ELEM;
    __shared__ float s_as[BM][2];
    __shared__ float s_ad[BM][2];

    const int tid = threadIdx.x;
    const int lane = tid & 31;
    const int wid = tid >> 5;
    const int warp_m = wid & 3;
    const int warp_n = wid >> 2;
    const int quad = lane >> 2;
    const int qt = lane & 3;
    const int r0 = blockIdx.x * BM;

    float acc[2][AN][4];
#pragma unroll
    for (int i = 0; i < 2; i++)
#pragma unroll
        for (int j = 0; j < AN; j++)
#pragma unroll
            for (int c = 0; c < 4; c++) acc[i][j][c] = 0.f;

    for (int k0 = 0; k0 < KD; k0 += KC) {
        // ---- A tile ----
#pragma unroll
        for (int it = 0; it < (BM * KC / 4) / 256; it++) {
            int idx = tid + it * 256;
            int row = idx >> 3;
            int kq = (idx & 7) * 4;
            float4 v = make_float4(0.f, 0.f, 0.f, 0.f);
            int gr = r0 + row;
            if (gr < NN) {
                const float* ap;
                if (AMODE == 0) {
                    ap = (gr < NI) ? (Ei + (size_t)gr * 64)
                        : (gr < NI + NU) ? (Eu + (size_t)(gr - NI) * 64)
                                         : (Ef + (size_t)(gr - NI - NU) * 64);
                } else {
                    ap = ((AMODE == 1) ? g_x1 : g_x2) + (size_t)gr * KD;
                }
                v = *(const float4*)(ap + k0 + kq);
                if (AMODE != 0) {
                    v.x = fmaxf(v.x, 0.f); v.y = fmaxf(v.y, 0.f);
                    v.z = fmaxf(v.z, 0.f); v.w = fmaxf(v.w, 0.f);
                }
            }
            float hx, lx, hy, ly, hz, lz, hw, lw;
            bf_hilo(v.x, hx, lx); bf_hilo(v.y, hy, ly);
            bf_hilo(v.z, hz, lz); bf_hilo(v.w, hw, lw);
            uint32_t* ph = &As_h[row * KAP + (kq >> 1)];
            uint32_t* pl = &As_l[row * KAP + (kq >> 1)];
            *(uint2*)ph = make_uint2(bfpack(hx, hy), bfpack(hz, hw));
            *(uint2*)pl = make_uint2(bfpack(lx, ly), bfpack(lz, lw));
        }
        // ---- B tile ----
#pragma unroll
        for (int it = 0; it < ((KC / 2) * (NC / 4)) / 256; it++) {
            int idx = tid + it * 256;
            int kk2 = idx / (NC / 4);
            int nq = (idx % (NC / 4)) * 4;
            float4 v0 = *(const float4*)&W[(size_t)(k0 + 2 * kk2) * NC + nq];
            float4 v1 = *(const float4*)&W[(size_t)(k0 + 2 * kk2 + 1) * NC + nq];
            float h0x, l0x, h0y, l0y, h0z, l0z, h0w, l0w;
            float h1x, l1x, h1y, l1y, h1z, l1z, h1w, l1w;
            bf_hilo(v0.x, h0x, l0x); bf_hilo(v0.y, h0y, l0y);
            bf_hilo(v0.z, h0z, l0z); bf_hilo(v0.w, h0w, l0w);
            bf_hilo(v1.x, h1x, l1x); bf_hilo(v1.y, h1y, l1y);
            bf_hilo(v1.z, h1z, l1z); bf_hilo(v1.w, h1w, l1w);
            *(uint4*)&Bs_h[kk2 * NCP + nq] =
                make_uint4(bfpack(h0x, h1x), bfpack(h0y, h1y),
                           bfpack(h0z, h1z), bfpack(h0w, h1w));
            *(uint4*)&Bs_l[kk2 * NCP + nq] =
                make_uint4(bfpack(l0x, l1x), bfpack(l0y, l1y),
                           bfpack(l0z, l1z), bfpack(l0w, l1w));
        }
        __syncthreads();

        // ---- compute ----
#pragma unroll
        for (int s = 0; s < KC / 16; s++) {
            uint32_t ah[2][4], al[2][4];
#pragma unroll
            for (int i = 0; i < 2; i++) {
                int row = warp_m * 32 + i * 16 + quad;
                int c0 = s * 8 + qt;
                ah[i][0] = As_h[row * KAP + c0];
                ah[i][1] = As_h[(row + 8) * KAP + c0];
                ah[i][2] = As_h[row * KAP + c0 + 4];
                ah[i][3] = As_h[(row + 8) * KAP + c0 + 4];
                al[i][0] = As_l[row * KAP + c0];
                al[i][1] = As_l[(row + 8) * KAP + c0];
                al[i][2] = As_l[row * KAP + c0 + 4];
                al[i][3] = As_l[(row + 8) * KAP + c0 + 4];
            }
#pragma unroll
            for (int j = 0; j < AN; j++) {
                int n = warp_n * WN + j * 8 + quad;
                int c0 = s * 8 + qt;
                uint32_t bh[2], bl[2];
                bh[0] = Bs_h[c0 * NCP + n];
                bh[1] = Bs_h[(c0 + 4) * NCP + n];
                bl[0] = Bs_l[c0 * NCP + n];
                bl[1] = Bs_l[(c0 + 4) * NCP + n];
#pragma unroll
                for (int i = 0; i < 2; i++) {
                    mma16(acc[i][j], ah[i], bh);
                    mma16(acc[i][j], ah[i], bl);
                    mma16(acc[i][j], al[i], bh);
                }
            }
        }
        __syncthreads();
    }

    // ---- epilogue: store fp16 g_xwh + fused att partial dots ----
    float pas0[2] = {0.f, 0.f}, pas1[2] = {0.f, 0.f};
    float pad0[2] = {0.f, 0.f}, pad1[2] = {0.f, 0.f};
#pragma unroll
    for (int i = 0; i < 2; i++) {
        int row = r0 + warp_m * 32 + i * 16 + quad;
#pragma unroll
        for (int j = 0; j < AN; j++) {
            int col = warp_n * WN + j * 8 + qt * 2;
            float ws0 = att_s[col & 63];
            float ws1 = att_s[(col & 63) + 1];
            float wd0 = att_d[col & 63];
            float wd1 = att_d[(col & 63) + 1];
            if (H == 2 && col >= 64) {
                ws0 = att_s[64 + (col & 63)]; ws1 = att_s[64 + (col & 63) + 1];
                wd0 = att_d[64 + (col & 63)]; wd1 = att_d[64 + (col & 63) + 1];
            }
            pas0[i] += acc[i][j][0] * ws0 + acc[i][j][1] * ws1;
            pas1[i] += acc[i][j][2] * ws0 + acc[i][j][3] * ws1;
            pad0[i] += acc[i][j][0] * wd0 + acc[i][j][1] * wd1;
            pad1[i] += acc[i][j][2] * wd0 + acc[i][j][3] * wd1;
            if (row < NN) {
                __half2 h2 = __floats2half2_rn(acc[i][j][0], acc[i][j][1]);
                *(__half2*)&g_xwh[(size_t)row * NC + col] = h2;
            }
            if (row + 8 < NN) {
                __half2 h2 = __floats2half2_rn(acc[i][j][2], acc[i][j][3]);
                *(__half2*)&g_xwh[(size_t)(row + 8) * NC + col] = h2;
            }
        }
    }
#pragma unroll
    for (int off = 1; off <= 2; off <<= 1) {
#pragma unroll
        for (int i = 0; i < 2; i++) {
            pas0[i] += __shfl_xor_sync(0xffffffffu, pas0[i], off);
            pas1[i] += __shfl_xor_sync(0xffffffffu, pas1[i], off);
            pad0[i] += __shfl_xor_sync(0xffffffffu, pad0[i], off);
            pad1[i] += __shfl_xor_sync(0xffffffffu, pad1[i], off);
        }
    }
    if (qt == 0) {
#pragma unroll
        for (int i = 0; i < 2; i++) {
            int lr = warp_m * 32 + i * 16 + quad;
            s_as[lr][warp_n] = pas0[i];
            s_as[lr + 8][warp_n] = pas1[i];
            s_ad[lr][warp_n] = pad0[i];
            s_ad[lr + 8][warp_n] = pad1[i];
        }
    }
    __syncthreads();
    if (H == 2) {
        if (tid < 256) {
            int r = tid >> 1, h = tid & 1;
            int gr = r0 + r;
            if (gr < NN) {
                g_as[(size_t)gr * 2 + h] = s_as[r][h];
                g_ad[(size_t)gr * 2 + h] = s_ad[r][h];
            }
        }
    } else {
        if (tid < 128) {
            int gr = r0 + tid;
            if (gr < NN) {
                g_as[gr] = s_as[tid][0] + s_as[tid][1];
                g_ad[gr] = s_ad[tid][0] + s_ad[tid][1];
            }
        }
    }
}

// ===== fully-fused edge kernel: score + softmax + alpha + aggregation =====
template <int H, int SEL>
__global__ void k_edge(const float* __restrict__ bias, float* __restrict__ alpha_out) {
    int node = (blockIdx.x * blockDim.x + threadIdx.x) >> 5;
    int lane = threadIdx.x & 31;
    if (node >= NN) return;
    const int s0 = g_off[node], s1 = g_off[node + 1];
    const int deg = s1 - s0;
    float ad0, ad1 = 0.f;
    if (H == 2) {
        float2 t = *(const float2*)&g_ad[(size_t)node * 2];
        ad0 = t.x; ad1 = t.y;
    } else ad0 = g_ad[node];

    float acc0 = 0.f, acc1 = 0.f, acc2 = 0.f, acc3 = 0.f;

    if (deg <= 32) {
        const bool valid = lane < deg;
        int jj = s0 + lane;
        int srcv = 0, ev = 0;
        float e0 = -INFINITY, e1 = -INFINITY;
        if (valid) {
            srcv = g_srcid[jj];
            ev = g_eid[jj];
            if (H == 2) {
                float2 a = *(const float2*)&g_as[(size_t)srcv * 2];
                e0 = lrelu(a.x + ad0); e1 = lrelu(a.y + ad1);
            } else {
                e0 = lrelu(g_as[srcv] + ad0);
            }
        }
        float m0 = e0, m1 = e1;
#pragma unroll
        for (int o = 16; o > 0; o >>= 1) {
            m0 = fmaxf(m0, __shfl_xor_sync(0xffffffffu, m0, o));
            if (H == 2) m1 = fmaxf(m1, __shfl_xor_sync(0xffffffffu, m1, o));
        }
        float p0 = valid ? expf(e0 - m0) : 0.f;
        float p1 = (H == 2 && valid) ? expf(e1 - m1) : 0.f;
        float sum0 = p0, sum1 = p1;
#pragma unroll
        for (int o = 16; o > 0; o >>= 1) {
            sum0 += __shfl_xor_sync(0xffffffffu, sum0, o);
            if (H == 2) sum1 += __shfl_xor_sync(0xffffffffu, sum1, o);
        }
        float a0v = p0 / (sum0 + 1e-16f);
        float a1v = (H == 2) ? p1 / (sum1 + 1e-16f) : 0.f;
        if (valid) {
            if (H == 2)
                *(float2*)&alpha_out[(size_t)ev * 2] = make_float2(a0v, a1v);
            else
                alpha_out[ev] = a0v;
        }
        for (int t = 0; t < deg; t++) {
            int src = __shfl_sync(0xffffffffu, srcv, t);
            float a0 = __shfl_sync(0xffffffffu, a0v, t);
            if (H == 2) {
                float a1 = __shfl_sync(0xffffffffu, a1v, t);
                uint2 u = *(const uint2*)&g_xwh[(size_t)src * 128 + lane * 4];
                float2 f01 = __half22float2(*(__half2*)&u.x);
                float2 f23 = __half22float2(*(__half2*)&u.y);
                float a = (lane < 16) ? a0 : a1;
                acc0 += a * f01.x; acc1 += a * f01.y;
                acc2 += a * f23.x; acc3 += a * f23.y;
            } else {
                uint32_t u = *(const uint32_t*)&g_xwh[(size_t)src * 64 + lane * 2];
                float2 f = __half22float2(*(__half2*)&u);
                acc0 += a0 * f.x; acc1 += a0 * f.y;
            }
        }
    } else {
        float m0 = -INFINITY, m1 = -INFINITY;
        for (int j = s0 + lane; j < s1; j += 32) {
            int src = g_srcid[j];
            if (H == 2) {
                float2 a = *(const float2*)&g_as[(size_t)src * 2];
                float e0 = lrelu(a.x + ad0), e1 = lrelu(a.y + ad1);
                *(float2*)&g_esc[(size_t)j * 2] = make_float2(e0, e1);
                m0 = fmaxf(m0, e0); m1 = fmaxf(m1, e1);
            } else {
                float e0 = lrelu(g_as[src] + ad0);
                g_esc[j] = e0;
                m0 = fmaxf(m0, e0);
            }
        }
#pragma unroll
        for (int o = 16; o > 0; o >>= 1) {
            m0 = fmaxf(m0, __shfl_xor_sync(0xffffffffu, m0, o));
            if (H == 2) m1 = fmaxf(m1, __shfl_xor_sync(0xffffffffu, m1, o));
        }
        float sum0 = 0.f, sum1 = 0.f;
        for (int j = s0 + lane; j < s1; j += 32) {
            if (H == 2) {
                float2 t = *(const float2*)&g_esc[(size_t)j * 2];
                sum0 += expf(t.x - m0); sum1 += expf(t.y - m1);
            } else sum0 += expf(g_esc[j] - m0);
        }
#pragma unroll
        for (int o = 16; o > 0; o >>= 1) {
            sum0 += __shfl_xor_sync(0xffffffffu, sum0, o);
            if (H == 2) sum1 += __shfl_xor_sync(0xffffffffu, sum1, o);
        }
        const float inv0 = 1.f / (sum0 + 1e-16f);
        const float inv1 = (H == 2) ? 1.f / (sum1 + 1e-16f) : 0.f;
        for (int base = s0; base < s1; base += 32) {
            int jj = base + lane;
            int srcv = 0;
            float a0v = 0.f, a1v = 0.f;
            if (jj < s1) {
                srcv = g_srcid[jj];
                int e = g_eid[jj];
                if (H == 2) {
                    float2 t = *(const float2*)&g_esc[(size_t)jj * 2];
                    a0v = expf(t.x - m0) * inv0;
                    a1v = expf(t.y - m1) * inv1;
                    *(float2*)&alpha_out[(size_t)e * 2] = make_float2(a0v, a1v);
                } else {
                    a0v = expf(g_esc[jj] - m0) * inv0;
                    alpha_out[e] = a0v;
                }
            }
            int n = min(32, s1 - base);
            for (int t = 0; t < n; t++) {
                int src = __shfl_sync(0xffffffffu, srcv, t);
                float a0 = __shfl_sync(0xffffffffu, a0v, t);
                if (H == 2) {
                    float a1 = __shfl_sync(0xffffffffu, a1v, t);
                    uint2 u = *(const uint2*)&g_xwh[(size_t)src * 128 + lane * 4];
                    float2 f01 = __half22float2(*(__half2*)&u.x);
                    float2 f23 = __half22float2(*(__half2*)&u.y);
                    float a = (lane < 16) ? a0 : a1;
                    acc0 += a * f01.x; acc1 += a * f01.y;
                    acc2 += a * f23.x; acc3 += a * f23.y;
                } else {
                    uint32_t u = *(const uint32_t*)&g_xwh[(size_t)src * 64 + lane * 2];
                    float2 f = __half22float2(*(__half2*)&u);
                    acc0 += a0 * f.x; acc1 += a0 * f.y;
                }
            }
        }
    }

    if (H == 2) {
        float4 b = *(const float4*)&bias[lane * 4];
        float* out = (SEL == 1) ? g_x1 : g_x2;
        *(float4*)&out[(size_t)node * 128 + lane * 4] =
            make_float4(acc0 + b.x, acc1 + b.y, acc2 + b.z, acc3 + b.w);
    } else {
        float2 b = *(const float2*)&bias[lane * 2];
        *(float2*)&g_x3[(size_t)node * 64 + lane * 2] =
            make_float2(acc0 + b.x, acc1 + b.y);
    }
}

// ================= final combine + output slices =================
__global__ void k_final(const float* __restrict__ Ei, const float* __restrict__ Eu,
                        const float* __restrict__ Ef, float* __restrict__ out) {
    int t = blockIdx.x * blockDim.x + threadIdx.x;
    if (t >= NN * 16) return;
    int n = t >> 4;
    int dq = (t & 15) * 4;
    const float* x0p = (n < NI) ? (Ei + (size_t)n * 64)
                     : (n < NI + NU) ? (Eu + (size_t)(n - NI) * 64)
                                     : (Ef + (size_t)(n - NI - NU) * 64);
    float4 x0 = *(const float4*)(x0p + dq);
    float4 a = *(const float4*)&g_x1[(size_t)n * 128 + dq];
    float4 b = *(const float4*)&g_x1[(size_t)n * 128 + 64 + dq];
    float4 c = *(const float4*)&g_x2[(size_t)n * 128 + dq];
    float4 d = *(const float4*)&g_x2[(size_t)n * 128 + 64 + dq];
    float4 x3 = *(const float4*)&g_x3[(size_t)n * 64 + dq];
    float4 f;
    f.x = (x0.x + 0.5f * (a.x + b.x) + 0.5f * (c.x + d.x) + x3.x) * 0.25f;
    f.y = (x0.y + 0.5f * (a.y + b.y) + 0.5f * (c.y + d.y) + x3.y) * 0.25f;
    f.z = (x0.z + 0.5f * (a.z + b.z) + 0.5f * (c.z + d.z) + x3.z) * 0.25f;
    f.w = (x0.w + 0.5f * (a.w + b.w) + 0.5f * (c.w + d.w) + x3.w) * 0.25f;
    *(float4*)&out[OFF_FINAL + (size_t)n * 64 + dq] = f;
    size_t so = (n < NI) ? (OFF_ITEM + (size_t)n * 64)
              : (n < NI + NU) ? (OFF_USER + (size_t)(n - NI) * 64)
                              : (OFF_FET + (size_t)(n - NI - NU) * 64);
    *(float4*)&out[so + dq] = f;
}

// ================= host launcher =================
extern "C" void kernel_launch(void* const* d_in, const int* in_sizes, int n_in,
                              void* d_out, int out_size) {
    const int*   ei   = (const int*)d_in[0];
    const float* embi = (const float*)d_in[1];
    const float* embu = (const float*)d_in[2];
    const float* embf = (const float*)d_in[3];
    const float* W1   = (const float*)d_in[4];
    const float* as1  = (const float*)d_in[5];
    const float* ad1  = (const float*)d_in[6];
    const float* b1   = (const float*)d_in[7];
    const float* W2   = (const float*)d_in[8];
    const float* as2  = (const float*)d_in[9];
    const float* ad2  = (const float*)d_in[10];
    const float* b2   = (const float*)d_in[11];
    const float* W3   = (const float*)d_in[12];
    const float* as3  = (const float*)d_in[13];
    const float* ad3  = (const float*)d_in[14];
    const float* b3   = (const float*)d_in[15];
    float* out = (float*)d_out;

    const int SCAN_BLOCKS = (NN + 1023) / 1024;  // 98
    const int GEMM_GRID = (NN + 127) / 128;      // 782
    const int WARP_GRID = (NN + 7) / 8;          // 12500

    // dynamic smem (bytes): A hi+lo = 2*128*20; B hi+lo = 2*16*(NC+8) uints
    const int SM_128 = (2 * 128 * 20 + 2 * 16 * 136) * 4;  // 37888
    const int SM_64  = (2 * 128 * 20 + 2 * 16 * 72) * 4;   // 29696
    cudaFuncSetAttribute(k_gemm_mma<64, 128, 0, 2>,
                         cudaFuncAttributeMaxDynamicSharedMemorySize, SM_128);
    cudaFuncSetAttribute(k_gemm_mma<128, 128, 1, 2>,
                         cudaFuncAttributeMaxDynamicSharedMemorySize, SM_128);
    cudaFuncSetAttribute(k_gemm_mma<128, 64, 2, 1>,
                         cudaFuncAttributeMaxDynamicSharedMemorySize, SM_64);

    // my-launch #4 = layer-1 GEMM (ncu profiles absolute #6 = my #4)
    k_zero_cnt<<<(NN + 255) / 256, 256>>>();                               // 1
    k_count<<<2048, 256>>>(ei);                                            // 2
    k_scan1<<<SCAN_BLOCKS, 1024>>>();                                      // 3
    k_gemm_mma<64, 128, 0, 2><<<GEMM_GRID, 256, SM_128>>>(embi, embu, embf,
                                                          W1, as1, ad1);   // 4
    k_scan2<<<1, 128>>>(SCAN_BLOCKS);                                      // 5
    k_scan3<<<SCAN_BLOCKS, 1024>>>();                                      // 6
    k_scatter<<<2048, 256>>>(ei);                                          // 7

    // ---- layer 1 ----
    k_edge<2, 1><<<WARP_GRID, 256>>>(b1, out + OFF_A1);

    // ---- layer 2 ----
    k_gemm_mma<128, 128, 1, 2><<<GEMM_GRID, 256, SM_128>>>(embi, embu, embf,
                                                           W2, as2, ad2);
    k_edge<2, 2><<<WARP_GRID, 256>>>(b2, out + OFF_A2);

    // ---- layer 3 ----
    k_gemm_mma<128, 64, 2, 1><<<GEMM_GRID, 256, SM_64>>>(embi, embu, embf,
                                                         W3, as3, ad3);
    k_edge<1, 3><<<WARP_GRID, 256>>>(b3, out + OFF_A3);

    // ---- final combine ----
    k_final<<<(NN * 16 + 255) / 256, 256>>>(embi, embu, embf, out);
}

// round 12
// speedup vs baseline: 1.0857x; 1.0857x over previous
#include <cuda_runtime.h>
#include <cuda_bf16.h>
#include <cuda_fp16.h>
#include <cstdint>

#define NI 40000
#define NU 30000
#define NF 30000
#define NN 100000
#define EE 1200000
#define ET (EE + NN)
#define NEG 0.2f

// ---- output layout (tuple order, flattened) ----
static const size_t OFF_ITEM  = 0;
static const size_t OFF_USER  = OFF_ITEM + (size_t)NI * 64;
static const size_t OFF_FET   = OFF_USER + (size_t)NU * 64;
static const size_t OFF_FINAL = OFF_FET  + (size_t)NF * 64;
static const size_t OFF_A1    = OFF_FINAL + (size_t)NN * 64;
static const size_t OFF_A2    = OFF_A1 + (size_t)ET * 2;
static const size_t OFF_A3    = OFF_A2 + (size_t)ET * 2;

// ---- scratch (device globals; no allocation allowed) ----
__device__ __half g_xwh[(size_t)NN * 128];
__device__ float g_x1[(size_t)NN * 128];
__device__ float g_x2[(size_t)NN * 128];
__device__ float g_as[(size_t)NN * 2];
__device__ float g_ad[(size_t)NN * 2];
__device__ float g_esc[(size_t)ET * 2];
__device__ int   g_cnt[NN];
__device__ int   g_off[NN + 1];
__device__ int   g_cur[NN];
__device__ int   g_eid[ET];
__device__ int   g_srcid[ET];
__device__ int   g_bsum[128];

__device__ __forceinline__ int edge_src(const int* ei, int e) {
    return (e < EE) ? ei[e] : (e - EE);
}
__device__ __forceinline__ int edge_dst(const int* ei, int e) {
    return (e < EE) ? ei[EE + e] : (e - EE);
}
__device__ __forceinline__ float lrelu(float x) { return x > 0.f ? x : NEG * x; }

// ---- bf16 split helpers (GEMM inputs) ----
__device__ __forceinline__ void bf_hilo(float x, float& h, float& l) {
    __nv_bfloat16 hb = __float2bfloat16_rn(x);
    h = __bfloat162float(hb);
    l = x - h;
}
__device__ __forceinline__ uint32_t bfpack(float lo_elem, float hi_elem) {
    __nv_bfloat162 t = __floats2bfloat162_rn(lo_elem, hi_elem);
    return *(uint32_t*)&t;
}
__device__ __forceinline__ void mma16(float* d, const uint32_t* a, const uint32_t* b) {
    asm volatile(
        "mma.sync.aligned.m16n8k16.row.col.f32.bf16.bf16.f32 "
        "{%0,%1,%2,%3}, {%4,%5,%6,%7}, {%8,%9}, {%0,%1,%2,%3};"
        : "+f"(d[0]), "+f"(d[1]), "+f"(d[2]), "+f"(d[3])
        : "r"(a[0]), "r"(a[1]), "r"(a[2]), "r"(a[3]), "r"(b[0]), "r"(b[1]));
}

// ================= CSR build =================
__global__ void k_zero_cnt() {
    int i = blockIdx.x * blockDim.x + threadIdx.x;
    if (i < NN) g_cnt[i] = 0;
}

__global__ void k_count(const int* __restrict__ ei) {
    for (int e = blockIdx.x * blockDim.x + threadIdx.x; e < ET;
         e += gridDim.x * blockDim.x)
        atomicAdd(&g_cnt[edge_dst(ei, e)], 1);
}

__global__ void k_scan1() {
    __shared__ int sh[1024];
    int i = blockIdx.x * 1024 + threadIdx.x;
    int v = (i < NN) ? g_cnt[i] : 0;
    sh[threadIdx.x] = v;
    __syncthreads();
    for (int o = 1; o < 1024; o <<= 1) {
        int t = (threadIdx.x >= (unsigned)o) ? sh[threadIdx.x - o] : 0;
        __syncthreads();
        sh[threadIdx.x] += t;
        __syncthreads();
    }
    if (i < NN) g_off[i + 1] = sh[threadIdx.x];
    if (threadIdx.x == 1023) g_bsum[blockIdx.x] = sh[1023];
}

__global__ void k_scan2(int nb) {
    __shared__ int sh[128];
    int v = ((int)threadIdx.x < nb) ? g_bsum[threadIdx.x] : 0;
    sh[threadIdx.x] = v;
    __syncthreads();
    for (int o = 1; o < 128; o <<= 1) {
        int t = (threadIdx.x >= (unsigned)o) ? sh[threadIdx.x - o] : 0;
        __syncthreads();
        sh[threadIdx.x] += t;
        __syncthreads();
    }
    if ((int)threadIdx.x < nb) g_bsum[threadIdx.x] = sh[threadIdx.x] - v;
}

__global__ void k_scan3() {
    int i = blockIdx.x * 1024 + threadIdx.x;
    if (i < NN) {
        int v = g_off[i + 1] + g_bsum[blockIdx.x];
        g_off[i + 1] = v;
        if (i + 1 < NN) g_cur[i + 1] = v;
    }
    if (i == 0) { g_off[0] = 0; g_cur[0] = 0; }
}

__global__ void k_scatter(const int* __restrict__ ei) {
    for (int e = blockIdx.x * blockDim.x + threadIdx.x; e < ET;
         e += gridDim.x * blockDim.x) {
        int s = edge_src(ei, e);
        int d = edge_dst(ei, e);
        int pos = atomicAdd(&g_cur[d], 1);
        g_eid[pos] = e;
        g_srcid[pos] = s;
    }
}

// ========== 3xBF16 mma.sync GEMM (m16n8k16), KC=64: fewer sync rounds ==========
template <int KD, int NC, int AMODE, int H>
__global__ void __launch_bounds__(256, 2)
k_gemm_mma(const float* __restrict__ Ei, const float* __restrict__ Eu,
           const float* __restrict__ Ef, const float* __restrict__ W,
           const float* __restrict__ att_s, const float* __restrict__ att_d) {
    constexpr int BM = 128, KC = 64;
    constexpr int KAP = KC / 2 + 4;      // 36 uints (≡4 mod 32): conflict-free
    constexpr int NCP = NC + 8;          // ≡8 mod 32: conflict-free
    constexpr int WN = NC / 2;
    constexpr int AN = WN / 8;
    constexpr int A_ELEM = BM * KAP;
    constexpr int B_ELEM = (KC / 2) * NCP;

    extern __shared__ uint32_t smu[];
    uint32_t* As_h = smu;
    uint32_t* As_l = As_h + A_ELEM;
    uint32_t* Bs_h = As_l + A_ELEM;
    uint32_t* Bs_l = Bs_h + B_ELEM;
    __shared__ float s_as[BM][2];
    __shared__ float s_ad[BM][2];

    const int tid = threadIdx.x;
    const int lane = tid & 31;
    const int wid = tid >> 5;
    const int warp_m = wid & 3;
    const int warp_n = wid >> 2;
    const int quad = lane >> 2;
    const int qt = lane & 3;
    const int r0 = blockIdx.x * BM;

    float acc[2][AN][4];
#pragma unroll
    for (int i = 0; i < 2; i++)
#pragma unroll
        for (int j = 0; j < AN; j++)
#pragma unroll
            for (int c = 0; c < 4; c++) acc[i][j][c] = 0.f;

#pragma unroll
    for (int k0 = 0; k0 < KD; k0 += KC) {
        // ---- A tile: BM x KC ----
#pragma unroll
        for (int it = 0; it < (BM * KC / 4) / 256; it++) {
            int idx = tid + it * 256;
            int row = idx >> 4;            // KC/4 = 16 float4 slots per row
            int kq = (idx & 15) * 4;
            float4 v = make_float4(0.f, 0.f, 0.f, 0.f);
            int gr = r0 + row;
            if (gr < NN) {
                const float* ap;
                if (AMODE == 0) {
                    ap = (gr < NI) ? (Ei + (size_t)gr * 64)
                        : (gr < NI + NU) ? (Eu + (size_t)(gr - NI) * 64)
                                         : (Ef + (size_t)(gr - NI - NU) * 64);
                } else {
                    ap = ((AMODE == 1) ? g_x1 : g_x2) + (size_t)gr * KD;
                }
                v = *(const float4*)(ap + k0 + kq);
                if (AMODE != 0) {
                    v.x = fmaxf(v.x, 0.f); v.y = fmaxf(v.y, 0.f);
                    v.z = fmaxf(v.z, 0.f); v.w = fmaxf(v.w, 0.f);
                }
            }
            float hx, lx, hy, ly, hz, lz, hw, lw;
            bf_hilo(v.x, hx, lx); bf_hilo(v.y, hy, ly);
            bf_hilo(v.z, hz, lz); bf_hilo(v.w, hw, lw);
            uint32_t* ph = &As_h[row * KAP + (kq >> 1)];
            uint32_t* pl = &As_l[row * KAP + (kq >> 1)];
            *(uint2*)ph = make_uint2(bfpack(hx, hy), bfpack(hz, hw));
            *(uint2*)pl = make_uint2(bfpack(lx, ly), bfpack(lz, lw));
        }
        // ---- B tile: KC x NC -> [KC/2][NCP] k-pairs ----
#pragma unroll
        for (int it = 0; it < ((KC / 2) * (NC / 4)) / 256; it++) {
            int idx = tid + it * 256;
            int kk2 = idx / (NC / 4);
            int nq = (idx % (NC / 4)) * 4;
            float4 v0 = *(const float4*)&W[(size_t)(k0 + 2 * kk2) * NC + nq];
            float4 v1 = *(const float4*)&W[(size_t)(k0 + 2 * kk2 + 1) * NC + nq];
            float h0x, l0x, h0y, l0y, h0z, l0z, h0w, l0w;
            float h1x, l1x, h1y, l1y, h1z, l1z, h1w, l1w;
            bf_hilo(v0.x, h0x, l0x); bf_hilo(v0.y, h0y, l0y);
            bf_hilo(v0.z, h0z, l0z); bf_hilo(v0.w, h0w, l0w);
            bf_hilo(v1.x, h1x, l1x); bf_hilo(v1.y, h1y, l1y);
            bf_hilo(v1.z, h1z, l1z); bf_hilo(v1.w, h1w, l1w);
            *(uint4*)&Bs_h[kk2 * NCP + nq] =
                make_uint4(bfpack(h0x, h1x), bfpack(h0y, h1y),
                           bfpack(h0z, h1z), bfpack(h0w, h1w));
            *(uint4*)&Bs_l[kk2 * NCP + nq] =
                make_uint4(bfpack(l0x, l1x), bfpack(l0y, l1y),
                           bfpack(l0z, l1z), bfpack(l0w, l1w));
        }
        __syncthreads();

        // ---- compute: KC/16 = 4 k16 steps ----
#pragma unroll
        for (int s = 0; s < KC / 16; s++) {
            uint32_t ah[2][4], al[2][4];
#pragma unroll
            for (int i = 0; i < 2; i++) {
                int row = warp_m * 32 + i * 16 + quad;
                int c0 = s * 8 + qt;
                ah[i][0] = As_h[row * KAP + c0];
                ah[i][1] = As_h[(row + 8) * KAP + c0];
                ah[i][2] = As_h[row * KAP + c0 + 4];
                ah[i][3] = As_h[(row + 8) * KAP + c0 + 4];
                al[i][0] = As_l[row * KAP + c0];
                al[i][1] = As_l[(row + 8) * KAP + c0];
                al[i][2] = As_l[row * KAP + c0 + 4];
                al[i][3] = As_l[(row + 8) * KAP + c0 + 4];
            }
#pragma unroll
            for (int j = 0; j < AN; j++) {
                int n = warp_n * WN + j * 8 + quad;
                int c0 = s * 8 + qt;
                uint32_t bh[2], bl[2];
                bh[0] = Bs_h[c0 * NCP + n];
                bh[1] = Bs_h[(c0 + 4) * NCP + n];
                bl[0] = Bs_l[c0 * NCP + n];
                bl[1] = Bs_l[(c0 + 4) * NCP + n];
#pragma unroll
                for (int i = 0; i < 2; i++) {
                    mma16(acc[i][j], ah[i], bh);
                    mma16(acc[i][j], ah[i], bl);
                    mma16(acc[i][j], al[i], bh);
                }
            }
        }
        if (k0 + KC < KD) __syncthreads();
    }

    // ---- epilogue: store fp16 g_xwh + fused att partial dots ----
    float pas0[2] = {0.f, 0.f}, pas1[2] = {0.f, 0.f};
    float pad0[2] = {0.f, 0.f}, pad1[2] = {0.f, 0.f};
#pragma unroll
    for (int i = 0; i < 2; i++) {
        int row = r0 + warp_m * 32 + i * 16 + quad;
#pragma unroll
        for (int j = 0; j < AN; j++) {
            int col = warp_n * WN + j * 8 + qt * 2;
            float ws0 = att_s[col & 63];
            float ws1 = att_s[(col & 63) + 1];
            float wd0 = att_d[col & 63];
            float wd1 = att_d[(col & 63) + 1];
            if (H == 2 && col >= 64) {
                ws0 = att_s[64 + (col & 63)]; ws1 = att_s[64 + (col & 63) + 1];
                wd0 = att_d[64 + (col & 63)]; wd1 = att_d[64 + (col & 63) + 1];
            }
            pas0[i] += acc[i][j][0] * ws0 + acc[i][j][1] * ws1;
            pas1[i] += acc[i][j][2] * ws0 + acc[i][j][3] * ws1;
            pad0[i] += acc[i][j][0] * wd0 + acc[i][j][1] * wd1;
            pad1[i] += acc[i][j][2] * wd0 + acc[i][j][3] * wd1;
            if (row < NN) {
                __half2 h2 = __floats2half2_rn(acc[i][j][0], acc[i][j][1]);
                *(__half2*)&g_xwh[(size_t)row * NC + col] = h2;
            }
            if (row + 8 < NN) {
                __half2 h2 = __floats2half2_rn(acc[i][j][2], acc[i][j][3]);
                *(__half2*)&g_xwh[(size_t)(row + 8) * NC + col] = h2;
            }
        }
    }
#pragma unroll
    for (int off = 1; off <= 2; off <<= 1) {
#pragma unroll
        for (int i = 0; i < 2; i++) {
            pas0[i] += __shfl_xor_sync(0xffffffffu, pas0[i], off);
            pas1[i] += __shfl_xor_sync(0xffffffffu, pas1[i], off);
            pad0[i] += __shfl_xor_sync(0xffffffffu, pad0[i], off);
            pad1[i] += __shfl_xor_sync(0xffffffffu, pad1[i], off);
        }
    }
    if (qt == 0) {
#pragma unroll
        for (int i = 0; i < 2; i++) {
            int lr = warp_m * 32 + i * 16 + quad;
            s_as[lr][warp_n] = pas0[i];
            s_as[lr + 8][warp_n] = pas1[i];
            s_ad[lr][warp_n] = pad0[i];
            s_ad[lr + 8][warp_n] = pad1[i];
        }
    }
    __syncthreads();
    if (H == 2) {
        if (tid < 256) {
            int r = tid >> 1, h = tid & 1;
            int gr = r0 + r;
            if (gr < NN) {
                g_as[(size_t)gr * 2 + h] = s_as[r][h];
                g_ad[(size_t)gr * 2 + h] = s_ad[r][h];
            }
        }
    } else {
        if (tid < 128) {
            int gr = r0 + tid;
            if (gr < NN) {
                g_as[gr] = s_as[tid][0] + s_as[tid][1];
                g_ad[gr] = s_ad[tid][0] + s_ad[tid][1];
            }
        }
    }
}

// ===== fully-fused edge kernel; SEL==3 also computes final + output slices =====
template <int H, int SEL>
__global__ void k_edge(const float* __restrict__ bias, float* __restrict__ alpha_out,
                       const float* __restrict__ Ei, const float* __restrict__ Eu,
                       const float* __restrict__ Ef, float* __restrict__ outbuf) {
    int node = (blockIdx.x * blockDim.x + threadIdx.x) >> 5;
    int lane = threadIdx.x & 31;
    if (node >= NN) return;
    const int s0 = g_off[node], s1 = g_off[node + 1];
    const int deg = s1 - s0;
    float ad0, ad1 = 0.f;
    if (H == 2) {
        float2 t = *(const float2*)&g_ad[(size_t)node * 2];
        ad0 = t.x; ad1 = t.y;
    } else ad0 = g_ad[node];

    float acc0 = 0.f, acc1 = 0.f, acc2 = 0.f, acc3 = 0.f;

    if (deg <= 32) {
        const bool valid = lane < deg;
        int jj = s0 + lane;
        int srcv = 0, ev = 0;
        float e0 = -INFINITY, e1 = -INFINITY;
        if (valid) {
            srcv = g_srcid[jj];
            ev = g_eid[jj];
            if (H == 2) {
                float2 a = *(const float2*)&g_as[(size_t)srcv * 2];
                e0 = lrelu(a.x + ad0); e1 = lrelu(a.y + ad1);
            } else {
                e0 = lrelu(g_as[srcv] + ad0);
            }
        }
        float m0 = e0, m1 = e1;
#pragma unroll
        for (int o = 16; o > 0; o >>= 1) {
            m0 = fmaxf(m0, __shfl_xor_sync(0xffffffffu, m0, o));
            if (H == 2) m1 = fmaxf(m1, __shfl_xor_sync(0xffffffffu, m1, o));
        }
        float p0 = valid ? expf(e0 - m0) : 0.f;
        float p1 = (H == 2 && valid) ? expf(e1 - m1) : 0.f;
        float sum0 = p0, sum1 = p1;
#pragma unroll
        for (int o = 16; o > 0; o >>= 1) {
            sum0 += __shfl_xor_sync(0xffffffffu, sum0, o);
            if (H == 2) sum1 += __shfl_xor_sync(0xffffffffu, sum1, o);
        }
        float a0v = p0 / (sum0 + 1e-16f);
        float a1v = (H == 2) ? p1 / (sum1 + 1e-16f) : 0.f;
        if (valid) {
            if (H == 2)
                *(float2*)&alpha_out[(size_t)ev * 2] = make_float2(a0v, a1v);
            else
                alpha_out[ev] = a0v;
        }
        for (int t = 0; t < deg; t++) {
            int src = __shfl_sync(0xffffffffu, srcv, t);
            float a0 = __shfl_sync(0xffffffffu, a0v, t);
            if (H == 2) {
                float a1 = __shfl_sync(0xffffffffu, a1v, t);
                uint2 u = *(const uint2*)&g_xwh[(size_t)src * 128 + lane * 4];
                float2 f01 = __half22float2(*(__half2*)&u.x);
                float2 f23 = __half22float2(*(__half2*)&u.y);
                float a = (lane < 16) ? a0 : a1;
                acc0 += a * f01.x; acc1 += a * f01.y;
                acc2 += a * f23.x; acc3 += a * f23.y;
            } else {
                uint32_t u = *(const uint32_t*)&g_xwh[(size_t)src * 64 + lane * 2];
                float2 f = __half22float2(*(__half2*)&u);
                acc0 += a0 * f.x; acc1 += a0 * f.y;
            }
        }
    } else {
        float m0 = -INFINITY, m1 = -INFINITY;
        for (int j = s0 + lane; j < s1; j += 32) {
            int src = g_srcid[j];
            if (H == 2) {
                float2 a = *(const float2*)&g_as[(size_t)src * 2];
                float e0 = lrelu(a.x + ad0), e1 = lrelu(a.y + ad1);
                *(float2*)&g_esc[(size_t)j * 2] = make_float2(e0, e1);
                m0 = fmaxf(m0, e0); m1 = fmaxf(m1, e1);
            } else {
                float e0 = lrelu(g_as[src] + ad0);
                g_esc[j] = e0;
                m0 = fmaxf(m0, e0);
            }
        }
#pragma unroll
        for (int o = 16; o > 0; o >>= 1) {
            m0 = fmaxf(m0, __shfl_xor_sync(0xffffffffu, m0, o));
            if (H == 2) m1 = fmaxf(m1, __shfl_xor_sync(0xffffffffu, m1, o));
        }
        float sum0 = 0.f, sum1 = 0.f;
        for (int j = s0 + lane; j < s1; j += 32) {
            if (H == 2) {
                float2 t = *(const float2*)&g_esc[(size_t)j * 2];
                sum0 += expf(t.x - m0); sum1 += expf(t.y - m1);
            } else sum0 += expf(g_esc[j] - m0);
        }
#pragma unroll
        for (int o = 16; o > 0; o >>= 1) {
            sum0 += __shfl_xor_sync(0xffffffffu, sum0, o);
            if (H == 2) sum1 += __shfl_xor_sync(0xffffffffu, sum1, o);
        }
        const float inv0 = 1.f / (sum0 + 1e-16f);
        const float inv1 = (H == 2) ? 1.f / (sum1 + 1e-16f) : 0.f;
        for (int base = s0; base < s1; base += 32) {
            int jj = base + lane;
            int srcv = 0;
            float a0v = 0.f, a1v = 0.f;
            if (jj < s1) {
                srcv = g_srcid[jj];
                int e = g_eid[jj];
                if (H == 2) {
                    float2 t = *(const float2*)&g_esc[(size_t)jj * 2];
                    a0v = expf(t.x - m0) * inv0;
                    a1v = expf(t.y - m1) * inv1;
                    *(float2*)&alpha_out[(size_t)e * 2] = make_float2(a0v, a1v);
                } else {
                    a0v = expf(g_esc[jj] - m0) * inv0;
                    alpha_out[e] = a0v;
                }
            }
            int n = min(32, s1 - base);
            for (int t = 0; t < n; t++) {
                int src = __shfl_sync(0xffffffffu, srcv, t);
                float a0 = __shfl_sync(0xffffffffu, a0v, t);
                if (H == 2) {
                    float a1 = __shfl_sync(0xffffffffu, a1v, t);
                    uint2 u = *(const uint2*)&g_xwh[(size_t)src * 128 + lane * 4];
                    float2 f01 = __half22float2(*(__half2*)&u.x);
                    float2 f23 = __half22float2(*(__half2*)&u.y);
                    float a = (lane < 16) ? a0 : a1;
                    acc0 += a * f01.x; acc1 += a * f01.y;
                    acc2 += a * f23.x; acc3 += a * f23.y;
                } else {
                    uint32_t u = *(const uint32_t*)&g_xwh[(size_t)src * 64 + lane * 2];
                    float2 f = __half22float2(*(__half2*)&u);
                    acc0 += a0 * f.x; acc1 += a0 * f.y;
                }
            }
        }
    }

    if (H == 2) {
        float4 b = *(const float4*)&bias[lane * 4];
        float* out = (SEL == 1) ? g_x1 : g_x2;
        *(float4*)&out[(size_t)node * 128 + lane * 4] =
            make_float4(acc0 + b.x, acc1 + b.y, acc2 + b.z, acc3 + b.w);
    } else {
        // SEL == 3: x3 in registers -> compute final + output slices directly
        float2 b = *(const float2*)&bias[lane * 2];
        float x3a = acc0 + b.x, x3b = acc1 + b.y;
        const int dq = lane * 2;
        const float* x0p = (node < NI) ? (Ei + (size_t)node * 64)
                         : (node < NI + NU) ? (Eu + (size_t)(node - NI) * 64)
                                            : (Ef + (size_t)(node - NI - NU) * 64);
        float2 x0 = *(const float2*)(x0p + dq);
        float2 a1 = *(const float2*)&g_x1[(size_t)node * 128 + dq];
        float2 b1 = *(const float2*)&g_x1[(size_t)node * 128 + 64 + dq];
        float2 a2 = *(const float2*)&g_x2[(size_t)node * 128 + dq];
        float2 b2 = *(const float2*)&g_x2[(size_t)node * 128 + 64 + dq];
        float2 f;
        f.x = (x0.x + 0.5f * (a1.x + b1.x) + 0.5f * (a2.x + b2.x) + x3a) * 0.25f;
        f.y = (x0.y + 0.5f * (a1.y + b1.y) + 0.5f * (a2.y + b2.y) + x3b) * 0.25f;
        *(float2*)&outbuf[OFF_FINAL + (size_t)node * 64 + dq] = f;
        size_t so = (node < NI) ? (OFF_ITEM + (size_t)node * 64)
                  : (node < NI + NU) ? (OFF_USER + (size_t)(node - NI) * 64)
                                     : (OFF_FET + (size_t)(node - NI - NU) * 64);
        *(float2*)&outbuf[so + dq] = f;
    }
}

// ================= host launcher =================
extern "C" void kernel_launch(void* const* d_in, const int* in_sizes, int n_in,
                              void* d_out, int out_size) {
    const int*   ei   = (const int*)d_in[0];
    const float* embi = (const float*)d_in[1];
    const float* embu = (const float*)d_in[2];
    const float* embf = (const float*)d_in[3];
    const float* W1   = (const float*)d_in[4];
    const float* as1  = (const float*)d_in[5];
    const float* ad1  = (const float*)d_in[6];
    const float* b1   = (const float*)d_in[7];
    const float* W2   = (const float*)d_in[8];
    const float* as2  = (const float*)d_in[9];
    const float* ad2  = (const float*)d_in[10];
    const float* b2   = (const float*)d_in[11];
    const float* W3   = (const float*)d_in[12];
    const float* as3  = (const float*)d_in[13];
    const float* ad3  = (const float*)d_in[14];
    const float* b3   = (const float*)d_in[15];
    float* out = (float*)d_out;

    const int SCAN_BLOCKS = (NN + 1023) / 1024;  // 98
    const int GEMM_GRID = (NN + 127) / 128;      // 782
    const int WARP_GRID = (NN + 7) / 8;          // 12500

    // dynamic smem (bytes): KC=64 -> A hi+lo = 2*128*36; B hi+lo = 2*32*(NC+8)
    const int SM_128 = (2 * 128 * 36 + 2 * 32 * 136) * 4;  // 71680
    const int SM_64  = (2 * 128 * 36 + 2 * 32 * 72) * 4;   // 55296
    cudaFuncSetAttribute(k_gemm_mma<64, 128, 0, 2>,
                         cudaFuncAttributeMaxDynamicSharedMemorySize, SM_128);
    cudaFuncSetAttribute(k_gemm_mma<128, 128, 1, 2>,
                         cudaFuncAttributeMaxDynamicSharedMemorySize, SM_128);
    cudaFuncSetAttribute(k_gemm_mma<128, 64, 2, 1>,
                         cudaFuncAttributeMaxDynamicSharedMemorySize, SM_64);

    // my-launch #4 = layer-1 GEMM (ncu profiles absolute #6 = my #4)
    k_zero_cnt<<<(NN + 255) / 256, 256>>>();                               // 1
    k_count<<<2048, 256>>>(ei);                                            // 2
    k_scan1<<<SCAN_BLOCKS, 1024>>>();                                      // 3
    k_gemm_mma<64, 128, 0, 2><<<GEMM_GRID, 256, SM_128>>>(embi, embu, embf,
                                                          W1, as1, ad1);   // 4
    k_scan2<<<1, 128>>>(SCAN_BLOCKS);                                      // 5
    k_scan3<<<SCAN_BLOCKS, 1024>>>();                                      // 6
    k_scatter<<<2048, 256>>>(ei);                                          // 7

    // ---- layer 1 ----
    k_edge<2, 1><<<WARP_GRID, 256>>>(b1, out + OFF_A1, embi, embu, embf, out);

    // ---- layer 2 ----
    k_gemm_mma<128, 128, 1, 2><<<GEMM_GRID, 256, SM_128>>>(embi, embu, embf,
                                                           W2, as2, ad2);
    k_edge<2, 2><<<WARP_GRID, 256>>>(b2, out + OFF_A2, embi, embu, embf, out);

    // ---- layer 3 (edge kernel also emits final + slices) ----
    k_gemm_mma<128, 64, 2, 1><<<GEMM_GRID, 256, SM_64>>>(embi, embu, embf,
                                                         W3, as3, ad3);
    k_edge<1, 3><<<WARP_GRID, 256>>>(b3, out + OFF_A3, embi, embu, embf, out);
}

// round 13
// speedup vs baseline: 1.1007x; 1.0138x over previous
#include <cuda_runtime.h>
#include <cuda_bf16.h>
#include <cuda_fp16.h>
#include <cstdint>

#define NI 40000
#define NU 30000
#define NF 30000
#define NN 100000
#define EE 1200000
#define ET (EE + NN)
#define NEG 0.2f

// ---- output layout (tuple order, flattened) ----
static const size_t OFF_ITEM  = 0;
static const size_t OFF_USER  = OFF_ITEM + (size_t)NI * 64;
static const size_t OFF_FET   = OFF_USER + (size_t)NU * 64;
static const size_t OFF_FINAL = OFF_FET  + (size_t)NF * 64;
static const size_t OFF_A1    = OFF_FINAL + (size_t)NN * 64;
static const size_t OFF_A2    = OFF_A1 + (size_t)ET * 2;
static const size_t OFF_A3    = OFF_A2 + (size_t)ET * 2;

// ---- scratch (device globals; no allocation allowed) ----
__device__ __half g_xwh[(size_t)NN * 128];
__device__ __half g_x1h[(size_t)NN * 128];
__device__ __half g_x2h[(size_t)NN * 128];
__device__ float g_as[(size_t)NN * 2];
__device__ float g_ad[(size_t)NN * 2];
__device__ float g_esc[(size_t)ET * 2];
__device__ int   g_cnt[NN];
__device__ int   g_off[NN + 1];
__device__ int   g_cur[NN];
__device__ int   g_eid[ET];
__device__ int   g_srcid[ET];
__device__ int   g_bsum[128];

__device__ __forceinline__ int edge_src(const int* ei, int e) {
    return (e < EE) ? ei[e] : (e - EE);
}
__device__ __forceinline__ int edge_dst(const int* ei, int e) {
    return (e < EE) ? ei[EE + e] : (e - EE);
}
__device__ __forceinline__ float lrelu(float x) { return x > 0.f ? x : NEG * x; }

// ---- bf16 split helpers (GEMM inputs) ----
__device__ __forceinline__ void bf_hilo(float x, float& h, float& l) {
    __nv_bfloat16 hb = __float2bfloat16_rn(x);
    h = __bfloat162float(hb);
    l = x - h;
}
__device__ __forceinline__ uint32_t bfpack(float lo_elem, float hi_elem) {
    __nv_bfloat162 t = __floats2bfloat162_rn(lo_elem, hi_elem);
    return *(uint32_t*)&t;
}
__device__ __forceinline__ void mma16(float* d, const uint32_t* a, const uint32_t* b) {
    asm volatile(
        "mma.sync.aligned.m16n8k16.row.col.f32.bf16.bf16.f32 "
        "{%0,%1,%2,%3}, {%4,%5,%6,%7}, {%8,%9}, {%0,%1,%2,%3};"
        : "+f"(d[0]), "+f"(d[1]), "+f"(d[2]), "+f"(d[3])
        : "r"(a[0]), "r"(a[1]), "r"(a[2]), "r"(a[3]), "r"(b[0]), "r"(b[1]));
}

// ================= CSR build =================
__global__ void k_zero_cnt() {
    int i = blockIdx.x * blockDim.x + threadIdx.x;
    if (i < NN) g_cnt[i] = 0;
}

__global__ void k_count(const int* __restrict__ ei) {
    for (int e = blockIdx.x * blockDim.x + threadIdx.x; e < ET;
         e += gridDim.x * blockDim.x)
        atomicAdd(&g_cnt[edge_dst(ei, e)], 1);
}

__global__ void k_scan1() {
    __shared__ int sh[1024];
    int i = blockIdx.x * 1024 + threadIdx.x;
    int v = (i < NN) ? g_cnt[i] : 0;
    sh[threadIdx.x] = v;
    __syncthreads();
    for (int o = 1; o < 1024; o <<= 1) {
        int t = (threadIdx.x >= (unsigned)o) ? sh[threadIdx.x - o] : 0;
        __syncthreads();
        sh[threadIdx.x] += t;
        __syncthreads();
    }
    if (i < NN) g_off[i + 1] = sh[threadIdx.x];
    if (threadIdx.x == 1023) g_bsum[blockIdx.x] = sh[1023];
}

__global__ void k_scan2(int nb) {
    __shared__ int sh[128];
    int v = ((int)threadIdx.x < nb) ? g_bsum[threadIdx.x] : 0;
    sh[threadIdx.x] = v;
    __syncthreads();
    for (int o = 1; o < 128; o <<= 1) {
        int t = (threadIdx.x >= (unsigned)o) ? sh[threadIdx.x - o] : 0;
        __syncthreads();
        sh[threadIdx.x] += t;
        __syncthreads();
    }
    if ((int)threadIdx.x < nb) g_bsum[threadIdx.x] = sh[threadIdx.x] - v;
}

__global__ void k_scan3() {
    int i = blockIdx.x * 1024 + threadIdx.x;
    if (i < NN) {
        int v = g_off[i + 1] + g_bsum[blockIdx.x];
        g_off[i + 1] = v;
        if (i + 1 < NN) g_cur[i + 1] = v;
    }
    if (i == 0) { g_off[0] = 0; g_cur[0] = 0; }
}

__global__ void k_scatter(const int* __restrict__ ei) {
    for (int e = blockIdx.x * blockDim.x + threadIdx.x; e < ET;
         e += gridDim.x * blockDim.x) {
        int s = edge_src(ei, e);
        int d = edge_dst(ei, e);
        int pos = atomicAdd(&g_cur[d], 1);
        g_eid[pos] = e;
        g_srcid[pos] = s;
    }
}

// ========== 3xBF16 mma.sync GEMM (m16n8k16), per-layer KC ==========
template <int KD, int NC, int AMODE, int H, int KC>
__global__ void __launch_bounds__(256, 2)
k_gemm_mma(const float* __restrict__ Ei, const float* __restrict__ Eu,
           const float* __restrict__ Ef, const float* __restrict__ W,
           const float* __restrict__ att_s, const float* __restrict__ att_d) {
    constexpr int BM = 128;
    constexpr int KAP = KC / 2 + 4;      // 20 or 36: conflict-free A stride
    constexpr int NCP = NC + 8;          // ≡8 mod 32: conflict-free B stride
    constexpr int WN = NC / 2;
    constexpr int AN = WN / 8;
    constexpr int A_ELEM = BM * KAP;
    constexpr int B_ELEM = (KC / 2) * NCP;
    constexpr int KQR = KC / 4;          // float4 slots per A row

    extern __shared__ uint32_t smu[];
    uint32_t* As_h = smu;
    uint32_t* As_l = As_h + A_ELEM;
    uint32_t* Bs_h = As_l + A_ELEM;
    uint32_t* Bs_l = Bs_h + B_ELEM;
    __shared__ float s_as[BM][2];
    __shared__ float s_ad[BM][2];

    const int tid = threadIdx.x;
    const int lane = tid & 31;
    const int wid = tid >> 5;
    const int warp_m = wid & 3;
    const int warp_n = wid >> 2;
    const int quad = lane >> 2;
    const int qt = lane & 3;
    const int r0 = blockIdx.x * BM;

    float acc[2][AN][4];
#pragma unroll
    for (int i = 0; i < 2; i++)
#pragma unroll
        for (int j = 0; j < AN; j++)
#pragma unroll
            for (int c = 0; c < 4; c++) acc[i][j][c] = 0.f;

#pragma unroll
    for (int k0 = 0; k0 < KD; k0 += KC) {
        // ---- A tile: BM x KC ----
#pragma unroll
        for (int it = 0; it < (BM * KQR) / 256; it++) {
            int idx = tid + it * 256;
            int row = idx / KQR;
            int kq = (idx % KQR) * 4;
            float4 v = make_float4(0.f, 0.f, 0.f, 0.f);
            int gr = r0 + row;
            if (gr < NN) {
                if (AMODE == 0) {
                    const float* ap = (gr < NI) ? (Ei + (size_t)gr * 64)
                        : (gr < NI + NU) ? (Eu + (size_t)(gr - NI) * 64)
                                         : (Ef + (size_t)(gr - NI - NU) * 64);
                    v = *(const float4*)(ap + k0 + kq);
                } else {
                    const __half* aph =
                        ((AMODE == 1) ? g_x1h : g_x2h) + (size_t)gr * KD;
                    uint2 u = *(const uint2*)(aph + k0 + kq);
                    float2 f01 = __half22float2(*(__half2*)&u.x);
                    float2 f23 = __half22float2(*(__half2*)&u.y);
                    v = make_float4(fmaxf(f01.x, 0.f), fmaxf(f01.y, 0.f),
                                    fmaxf(f23.x, 0.f), fmaxf(f23.y, 0.f));
                }
            }
            float hx, lx, hy, ly, hz, lz, hw, lw;
            bf_hilo(v.x, hx, lx); bf_hilo(v.y, hy, ly);
            bf_hilo(v.z, hz, lz); bf_hilo(v.w, hw, lw);
            uint32_t* ph = &As_h[row * KAP + (kq >> 1)];
            uint32_t* pl = &As_l[row * KAP + (kq >> 1)];
            *(uint2*)ph = make_uint2(bfpack(hx, hy), bfpack(hz, hw));
            *(uint2*)pl = make_uint2(bfpack(lx, ly), bfpack(lz, lw));
        }
        // ---- B tile: KC x NC -> [KC/2][NCP] k-pairs ----
#pragma unroll
        for (int it = 0; it < ((KC / 2) * (NC / 4)) / 256; it++) {
            int idx = tid + it * 256;
            int kk2 = idx / (NC / 4);
            int nq = (idx % (NC / 4)) * 4;
            float4 v0 = *(const float4*)&W[(size_t)(k0 + 2 * kk2) * NC + nq];
            float4 v1 = *(const float4*)&W[(size_t)(k0 + 2 * kk2 + 1) * NC + nq];
            float h0x, l0x, h0y, l0y, h0z, l0z, h0w, l0w;
            float h1x, l1x, h1y, l1y, h1z, l1z, h1w, l1w;
            bf_hilo(v0.x, h0x, l0x); bf_hilo(v0.y, h0y, l0y);
            bf_hilo(v0.z, h0z, l0z); bf_hilo(v0.w, h0w, l0w);
            bf_hilo(v1.x, h1x, l1x); bf_hilo(v1.y, h1y, l1y);
            bf_hilo(v1.z, h1z, l1z); bf_hilo(v1.w, h1w, l1w);
            *(uint4*)&Bs_h[kk2 * NCP + nq] =
                make_uint4(bfpack(h0x, h1x), bfpack(h0y, h1y),
                           bfpack(h0z, h1z), bfpack(h0w, h1w));
            *(uint4*)&Bs_l[kk2 * NCP + nq] =
                make_uint4(bfpack(l0x, l1x), bfpack(l0y, l1y),
                           bfpack(l0z, l1z), bfpack(l0w, l1w));
        }
        __syncthreads();

        // ---- compute: KC/16 k16 steps ----
#pragma unroll
        for (int s = 0; s < KC / 16; s++) {
            uint32_t ah[2][4], al[2][4];
#pragma unroll
            for (int i = 0; i < 2; i++) {
                int row = warp_m * 32 + i * 16 + quad;
                int c0 = s * 8 + qt;
                ah[i][0] = As_h[row * KAP + c0];
                ah[i][1] = As_h[(row + 8) * KAP + c0];
                ah[i][2] = As_h[row * KAP + c0 + 4];
                ah[i][3] = As_h[(row + 8) * KAP + c0 + 4];
                al[i][0] = As_l[row * KAP + c0];
                al[i][1] = As_l[(row + 8) * KAP + c0];
                al[i][2] = As_l[row * KAP + c0 + 4];
                al[i][3] = As_l[(row + 8) * KAP + c0 + 4];
            }
#pragma unroll
            for (int j = 0; j < AN; j++) {
                int n = warp_n * WN + j * 8 + quad;
                int c0 = s * 8 + qt;
                uint32_t bh[2], bl[2];
                bh[0] = Bs_h[c0 * NCP + n];
                bh[1] = Bs_h[(c0 + 4) * NCP + n];
                bl[0] = Bs_l[c0 * NCP + n];
                bl[1] = Bs_l[(c0 + 4) * NCP + n];
#pragma unroll
                for (int i = 0; i < 2; i++) {
                    mma16(acc[i][j], ah[i], bh);
                    mma16(acc[i][j], ah[i], bl);
                    mma16(acc[i][j], al[i], bh);
                }
            }
        }
        if (k0 + KC < KD) __syncthreads();
    }

    // ---- epilogue: store fp16 g_xwh + fused att partial dots ----
    float pas0[2] = {0.f, 0.f}, pas1[2] = {0.f, 0.f};
    float pad0[2] = {0.f, 0.f}, pad1[2] = {0.f, 0.f};
#pragma unroll
    for (int i = 0; i < 2; i++) {
        int row = r0 + warp_m * 32 + i * 16 + quad;
#pragma unroll
        for (int j = 0; j < AN; j++) {
            int col = warp_n * WN + j * 8 + qt * 2;
            float ws0 = att_s[col & 63];
            float ws1 = att_s[(col & 63) + 1];
            float wd0 = att_d[col & 63];
            float wd1 = att_d[(col & 63) + 1];
            if (H == 2 && col >= 64) {
                ws0 = att_s[64 + (col & 63)]; ws1 = att_s[64 + (col & 63) + 1];
                wd0 = att_d[64 + (col & 63)]; wd1 = att_d[64 + (col & 63) + 1];
            }
            pas0[i] += acc[i][j][0] * ws0 + acc[i][j][1] * ws1;
            pas1[i] += acc[i][j][2] * ws0 + acc[i][j][3] * ws1;
            pad0[i] += acc[i][j][0] * wd0 + acc[i][j][1] * wd1;
            pad1[i] += acc[i][j][2] * wd0 + acc[i][j][3] * wd1;
            if (row < NN) {
                __half2 h2 = __floats2half2_rn(acc[i][j][0], acc[i][j][1]);
                *(__half2*)&g_xwh[(size_t)row * NC + col] = h2;
            }
            if (row + 8 < NN) {
                __half2 h2 = __floats2half2_rn(acc[i][j][2], acc[i][j][3]);
                *(__half2*)&g_xwh[(size_t)(row + 8) * NC + col] = h2;
            }
        }
    }
#pragma unroll
    for (int off = 1; off <= 2; off <<= 1) {
#pragma unroll
        for (int i = 0; i < 2; i++) {
            pas0[i] += __shfl_xor_sync(0xffffffffu, pas0[i], off);
            pas1[i] += __shfl_xor_sync(0xffffffffu, pas1[i], off);
            pad0[i] += __shfl_xor_sync(0xffffffffu, pad0[i], off);
            pad1[i] += __shfl_xor_sync(0xffffffffu, pad1[i], off);
        }
    }
    if (qt == 0) {
#pragma unroll
        for (int i = 0; i < 2; i++) {
            int lr = warp_m * 32 + i * 16 + quad;
            s_as[lr][warp_n] = pas0[i];
            s_as[lr + 8][warp_n] = pas1[i];
            s_ad[lr][warp_n] = pad0[i];
            s_ad[lr + 8][warp_n] = pad1[i];
        }
    }
    __syncthreads();
    if (H == 2) {
        if (tid < 256) {
            int r = tid >> 1, h = tid & 1;
            int gr = r0 + r;
            if (gr < NN) {
                g_as[(size_t)gr * 2 + h] = s_as[r][h];
                g_ad[(size_t)gr * 2 + h] = s_ad[r][h];
            }
        }
    } else {
        if (tid < 128) {
            int gr = r0 + tid;
            if (gr < NN) {
                g_as[gr] = s_as[tid][0] + s_as[tid][1];
                g_ad[gr] = s_ad[tid][0] + s_ad[tid][1];
            }
        }
    }
}

// ===== fully-fused edge kernel; SEL==3 also computes final + output slices =====
template <int H, int SEL>
__global__ void k_edge(const float* __restrict__ bias, float* __restrict__ alpha_out,
                       const float* __restrict__ Ei, const float* __restrict__ Eu,
                       const float* __restrict__ Ef, float* __restrict__ outbuf) {
    int node = (blockIdx.x * blockDim.x + threadIdx.x) >> 5;
    int lane = threadIdx.x & 31;
    if (node >= NN) return;
    const int s0 = g_off[node], s1 = g_off[node + 1];
    const int deg = s1 - s0;
    float ad0, ad1 = 0.f;
    if (H == 2) {
        float2 t = *(const float2*)&g_ad[(size_t)node * 2];
        ad0 = t.x; ad1 = t.y;
    } else ad0 = g_ad[node];

    float acc0 = 0.f, acc1 = 0.f, acc2 = 0.f, acc3 = 0.f;

    if (deg <= 32) {
        const bool valid = lane < deg;
        int jj = s0 + lane;
        int srcv = 0, ev = 0;
        float e0 = -INFINITY, e1 = -INFINITY;
        if (valid) {
            srcv = g_srcid[jj];
            ev = g_eid[jj];
            if (H == 2) {
                float2 a = *(const float2*)&g_as[(size_t)srcv * 2];
                e0 = lrelu(a.x + ad0); e1 = lrelu(a.y + ad1);
            } else {
                e0 = lrelu(g_as[srcv] + ad0);
            }
        }
        float m0 = e0, m1 = e1;
#pragma unroll
        for (int o = 16; o > 0; o >>= 1) {
            m0 = fmaxf(m0, __shfl_xor_sync(0xffffffffu, m0, o));
            if (H == 2) m1 = fmaxf(m1, __shfl_xor_sync(0xffffffffu, m1, o));
        }
        float p0 = valid ? expf(e0 - m0) : 0.f;
        float p1 = (H == 2 && valid) ? expf(e1 - m1) : 0.f;
        float sum0 = p0, sum1 = p1;
#pragma unroll
        for (int o = 16; o > 0; o >>= 1) {
            sum0 += __shfl_xor_sync(0xffffffffu, sum0, o);
            if (H == 2) sum1 += __shfl_xor_sync(0xffffffffu, sum1, o);
        }
        float a0v = p0 / (sum0 + 1e-16f);
        float a1v = (H == 2) ? p1 / (sum1 + 1e-16f) : 0.f;
        if (valid) {
            if (H == 2)
                *(float2*)&alpha_out[(size_t)ev * 2] = make_float2(a0v, a1v);
            else
                alpha_out[ev] = a0v;
        }
        for (int t = 0; t < deg; t++) {
            int src = __shfl_sync(0xffffffffu, srcv, t);
            float a0 = __shfl_sync(0xffffffffu, a0v, t);
            if (H == 2) {
                float a1 = __shfl_sync(0xffffffffu, a1v, t);
                uint2 u = *(const uint2*)&g_xwh[(size_t)src * 128 + lane * 4];
                float2 f01 = __half22float2(*(__half2*)&u.x);
                float2 f23 = __half22float2(*(__half2*)&u.y);
                float a = (lane < 16) ? a0 : a1;
                acc0 += a * f01.x; acc1 += a * f01.y;
                acc2 += a * f23.x; acc3 += a * f23.y;
            } else {
                uint32_t u = *(const uint32_t*)&g_xwh[(size_t)src * 64 + lane * 2];
                float2 f = __half22float2(*(__half2*)&u);
                acc0 += a0 * f.x; acc1 += a0 * f.y;
            }
        }
    } else {
        float m0 = -INFINITY, m1 = -INFINITY;
        for (int j = s0 + lane; j < s1; j += 32) {
            int src = g_srcid[j];
            if (H == 2) {
                float2 a = *(const float2*)&g_as[(size_t)src * 2];
                float e0 = lrelu(a.x + ad0), e1 = lrelu(a.y + ad1);
                *(float2*)&g_esc[(size_t)j * 2] = make_float2(e0, e1);
                m0 = fmaxf(m0, e0); m1 = fmaxf(m1, e1);
            } else {
                float e0 = lrelu(g_as[src] + ad0);
                g_esc[j] = e0;
                m0 = fmaxf(m0, e0);
            }
        }
#pragma unroll
        for (int o = 16; o > 0; o >>= 1) {
            m0 = fmaxf(m0, __shfl_xor_sync(0xffffffffu, m0, o));
            if (H == 2) m1 = fmaxf(m1, __shfl_xor_sync(0xffffffffu, m1, o));
        }
        float sum0 = 0.f, sum1 = 0.f;
        for (int j = s0 + lane; j < s1; j += 32) {
            if (H == 2) {
                float2 t = *(const float2*)&g_esc[(size_t)j * 2];
                sum0 += expf(t.x - m0); sum1 += expf(t.y - m1);
            } else sum0 += expf(g_esc[j] - m0);
        }
#pragma unroll
        for (int o = 16; o > 0; o >>= 1) {
            sum0 += __shfl_xor_sync(0xffffffffu, sum0, o);
            if (H == 2) sum1 += __shfl_xor_sync(0xffffffffu, sum1, o);
        }
        const float inv0 = 1.f / (sum0 + 1e-16f);
        const float inv1 = (H == 2) ? 1.f / (sum1 + 1e-16f) : 0.f;
        for (int base = s0; base < s1; base += 32) {
            int jj = base + lane;
            int srcv = 0;
            float a0v = 0.f, a1v = 0.f;
            if (jj < s1) {
                srcv = g_srcid[jj];
                int e = g_eid[jj];
                if (H == 2) {
                    float2 t = *(const float2*)&g_esc[(size_t)jj * 2];
                    a0v = expf(t.x - m0) * inv0;
                    a1v = expf(t.y - m1) * inv1;
                    *(float2*)&alpha_out[(size_t)e * 2] = make_float2(a0v, a1v);
                } else {
                    a0v = expf(g_esc[jj] - m0) * inv0;
                    alpha_out[e] = a0v;
                }
            }
            int n = min(32, s1 - base);
            for (int t = 0; t < n; t++) {
                int src = __shfl_sync(0xffffffffu, srcv, t);
                float a0 = __shfl_sync(0xffffffffu, a0v, t);
                if (H == 2) {
                    float a1 = __shfl_sync(0xffffffffu, a1v, t);
                    uint2 u = *(const uint2*)&g_xwh[(size_t)src * 128 + lane * 4];
                    float2 f01 = __half22float2(*(__half2*)&u.x);
                    float2 f23 = __half22float2(*(__half2*)&u.y);
                    float a = (lane < 16) ? a0 : a1;
                    acc0 += a * f01.x; acc1 += a * f01.y;
                    acc2 += a * f23.x; acc3 += a * f23.y;
                } else {
                    uint32_t u = *(const uint32_t*)&g_xwh[(size_t)src * 64 + lane * 2];
                    float2 f = __half22float2(*(__half2*)&u);
                    acc0 += a0 * f.x; acc1 += a0 * f.y;
                }
            }
        }
    }

    if (H == 2) {
        float4 b = *(const float4*)&bias[lane * 4];
        __half* out = (SEL == 1) ? g_x1h : g_x2h;
        __half2 h01 = __floats2half2_rn(acc0 + b.x, acc1 + b.y);
        __half2 h23 = __floats2half2_rn(acc2 + b.z, acc3 + b.w);
        uint2 u;
        u.x = *(uint32_t*)&h01;
        u.y = *(uint32_t*)&h23;
        *(uint2*)&out[(size_t)node * 128 + lane * 4] = u;
    } else {
        // SEL == 3: x3 in registers -> compute final + output slices directly
        float2 b = *(const float2*)&bias[lane * 2];
        float x3a = acc0 + b.x, x3b = acc1 + b.y;
        const int dq = lane * 2;
        const float* x0p = (node < NI) ? (Ei + (size_t)node * 64)
                         : (node < NI + NU) ? (Eu + (size_t)(node - NI) * 64)
                                            : (Ef + (size_t)(node - NI - NU) * 64);
        float2 x0 = *(const float2*)(x0p + dq);
        float2 a1 = __half22float2(*(const __half2*)&g_x1h[(size_t)node * 128 + dq]);
        float2 b1 = __half22float2(*(const __half2*)&g_x1h[(size_t)node * 128 + 64 + dq]);
        float2 a2 = __half22float2(*(const __half2*)&g_x2h[(size_t)node * 128 + dq]);
        float2 b2 = __half22float2(*(const __half2*)&g_x2h[(size_t)node * 128 + 64 + dq]);
        float2 f;
        f.x = (x0.x + 0.5f * (a1.x + b1.x) + 0.5f * (a2.x + b2.x) + x3a) * 0.25f;
        f.y = (x0.y + 0.5f * (a1.y + b1.y) + 0.5f * (a2.y + b2.y) + x3b) * 0.25f;
        *(float2*)&outbuf[OFF_FINAL + (size_t)node * 64 + dq] = f;
        size_t so = (node < NI) ? (OFF_ITEM + (size_t)node * 64)
                  : (node < NI + NU) ? (OFF_USER + (size_t)(node - NI) * 64)
                                     : (OFF_FET + (size_t)(node - NI - NU) * 64);
        *(float2*)&outbuf[so + dq] = f;
    }
}

// ================= host launcher =================
extern "C" void kernel_launch(void* const* d_in, const int* in_sizes, int n_in,
                              void* d_out, int out_size) {
    const int*   ei   = (const int*)d_in[0];
    const float* embi = (const float*)d_in[1];
    const float* embu = (const float*)d_in[2];
    const float* embf = (const float*)d_in[3];
    const float* W1   = (const float*)d_in[4];
    const float* as1  = (const float*)d_in[5];
    const float* ad1  = (const float*)d_in[6];
    const float* b1   = (const float*)d_in[7];
    const float* W2   = (const float*)d_in[8];
    const float* as2  = (const float*)d_in[9];
    const float* ad2  = (const float*)d_in[10];
    const float* b2   = (const float*)d_in[11];
    const float* W3   = (const float*)d_in[12];
    const float* as3  = (const float*)d_in[13];
    const float* ad3  = (const float*)d_in[14];
    const float* b3   = (const float*)d_in[15];
    float* out = (float*)d_out;

    const int SCAN_BLOCKS = (NN + 1023) / 1024;  // 98
    const int GEMM_GRID = (NN + 127) / 128;      // 782
    const int WARP_GRID = (NN + 7) / 8;          // 12500

    // smem: layer1 KC=32; layers 2/3 KC=64
    const int SM_L1 = (2 * 128 * 20 + 2 * 16 * 136) * 4;  // 37888
    const int SM_L2 = (2 * 128 * 36 + 2 * 32 * 136) * 4;  // 71680
    const int SM_L3 = (2 * 128 * 36 + 2 * 32 * 72) * 4;   // 55296
    cudaFuncSetAttribute(k_gemm_mma<64, 128, 0, 2, 32>,
                         cudaFuncAttributeMaxDynamicSharedMemorySize, SM_L1);
    cudaFuncSetAttribute(k_gemm_mma<128, 128, 1, 2, 64>,
                         cudaFuncAttributeMaxDynamicSharedMemorySize, SM_L2);
    cudaFuncSetAttribute(k_gemm_mma<128, 64, 2, 1, 64>,
                         cudaFuncAttributeMaxDynamicSharedMemorySize, SM_L3);

    // my-launch #4 = layer-1 GEMM (ncu profiles absolute #6 = my #4)
    k_zero_cnt<<<(NN + 255) / 256, 256>>>();                               // 1
    k_count<<<2048, 256>>>(ei);                                            // 2
    k_scan1<<<SCAN_BLOCKS, 1024>>>();                                      // 3
    k_gemm_mma<64, 128, 0, 2, 32><<<GEMM_GRID, 256, SM_L1>>>(embi, embu, embf,
                                                             W1, as1, ad1); // 4
    k_scan2<<<1, 128>>>(SCAN_BLOCKS);                                      // 5
    k_scan3<<<SCAN_BLOCKS, 1024>>>();                                      // 6
    k_scatter<<<2048, 256>>>(ei);                                          // 7

    // ---- layer 1 ----
    k_edge<2, 1><<<WARP_GRID, 256>>>(b1, out + OFF_A1, embi, embu, embf, out);

    // ---- layer 2 ----
    k_gemm_mma<128, 128, 1, 2, 64><<<GEMM_GRID, 256, SM_L2>>>(embi, embu, embf,
                                                              W2, as2, ad2);
    k_edge<2, 2><<<WARP_GRID, 256>>>(b2, out + OFF_A2, embi, embu, embf, out);

    // ---- layer 3 (edge kernel also emits final + slices) ----
    k_gemm_mma<128, 64, 2, 1, 64><<<GEMM_GRID, 256, SM_L3>>>(embi, embu, embf,
                                                             W3, as3, ad3);
    k_edge<1, 3><<<WARP_GRID, 256>>>(b3, out + OFF_A3, embi, embu, embf, out);
}